// round 2
// baseline (speedup 1.0000x reference)
#include <cuda_runtime.h>
#include <cstdint>

// ---------------------------------------------------------------------------
// CTRGC fused kernel, round 2: 2 output channels per thread to halve LDS/FLOP.
// out[n,o,t,w] = relu( sum_k sum_v (sum_c Weff[k][o,c] * x[n,c,t,v]) * M_k[v,w] + Ceff[o] )
// Shapes: N=128, Cin=Cout=64, T=256, V=18, K=3.
// ---------------------------------------------------------------------------

#define KNUM 3
#define CIN 64
#define COUT 64
#define TLEN 256
#define VD 18
#define VP 20          // padded row (16B-aligned rows)
#define TT 8           // t's per CTA tile
#define THREADS 256    // 8 t-groups x 32 o-pairs
#define NBLOCKS 1036
#define NTILES (128 * (TLEN / TT))

// prepped parameters (device globals: no allocation allowed)
__device__ float d_Wpack0[CIN * 32 * 4];    // [c][p][k0,k1,k2,pad] for o = 2p
__device__ float d_Wpack1[CIN * 32 * 4];    // for o = 2p+1
__device__ float d_Cf[COUT];
__device__ float d_M[KNUM * VD * VP];       // [k][v][w padded]

__global__ void prep_kernel(const float* __restrict__ A, const float* __restrict__ PA,
                            const float* __restrict__ Wta, const float* __restrict__ bta,
                            const float* __restrict__ g_ta, const float* __restrict__ b_ta,
                            const float* __restrict__ m_ta, const float* __restrict__ v_ta,
                            const float* __restrict__ g_bn, const float* __restrict__ b_bn,
                            const float* __restrict__ m_bn, const float* __restrict__ v_bn)
{
    int tid = threadIdx.x;
    for (int idx = tid; idx < CIN * 32; idx += blockDim.x) {
        int c = idx >> 5, p = idx & 31;
        for (int half = 0; half < 2; half++) {
            int o = 2 * p + half;
            float s2 = g_bn[o] * rsqrtf(v_bn[o] + 1e-5f);
            float w[3];
#pragma unroll
            for (int k = 0; k < KNUM; k++) {
                float s1 = g_ta[k * 64 + o] * rsqrtf(v_ta[k * 64 + o] + 1e-5f);
                w[k] = s2 * s1 * Wta[(k * 64 + o) * 64 + c];
            }
            float4 wv = make_float4(w[0], w[1], w[2], 0.0f);
            if (half == 0) *reinterpret_cast<float4*>(d_Wpack0 + idx * 4) = wv;
            else           *reinterpret_cast<float4*>(d_Wpack1 + idx * 4) = wv;
        }
    }
    if (tid < COUT) {
        int o = tid;
        float s2 = g_bn[o] * rsqrtf(v_bn[o] + 1e-5f);
        float acc = 0.0f;
        for (int k = 0; k < KNUM; k++) {
            float s1 = g_ta[k * 64 + o] * rsqrtf(v_ta[k * 64 + o] + 1e-5f);
            acc += s1 * bta[k * 64 + o] + b_ta[k * 64 + o] - m_ta[k * 64 + o] * s1;
        }
        d_Cf[o] = s2 * acc + b_bn[o] - m_bn[o] * s2;
    }
    for (int idx = tid; idx < KNUM * VD * VP; idx += blockDim.x) {
        int k = idx / (VD * VP);
        int r = idx - k * (VD * VP);
        int v = r / VP;
        int w = r - v * VP;
        d_M[idx] = (w < VD) ? (A[(k * VD + v) * VD + w] + PA[(k * VD + v) * VD + w]) : 0.0f;
    }
}

// ---- packed f32x2 helpers (Blackwell-only FFMA2, PTX path) ----
__device__ __forceinline__ unsigned long long pk2(float a, float b) {
    unsigned long long r;
    asm("mov.b64 %0, {%1,%2};" : "=l"(r) : "f"(a), "f"(b));
    return r;
}
__device__ __forceinline__ void upk2(unsigned long long p, float& a, float& b) {
    asm("mov.b64 {%0,%1}, %2;" : "=f"(a), "=f"(b) : "l"(p));
}
__device__ __forceinline__ unsigned long long fma2(unsigned long long a,
                                                   unsigned long long b,
                                                   unsigned long long c) {
    unsigned long long d;
    asm("fma.rn.f32x2 %0, %1, %2, %3;" : "=l"(d) : "l"(a), "l"(b), "l"(c));
    return d;
}

extern __shared__ float smem[];

__global__ __launch_bounds__(THREADS, 1)
void ctrgc_main(const float* __restrict__ x, float* __restrict__ out)
{
    // smem layout (floats): sW0 8192 | sW1 8192 | sM 1080 | sC 64 | sx 10240
    float* sW0 = smem;
    float* sW1 = sW0 + CIN * 32 * 4;
    float* sM  = sW1 + CIN * 32 * 4;
    float* sC  = sM + KNUM * VD * VP;
    float* sx  = sC + COUT;

    int tid = threadIdx.x;
    for (int i = tid; i < CIN * 32 * 4; i += THREADS) {
        sW0[i] = d_Wpack0[i];
        sW1[i] = d_Wpack1[i];
    }
    for (int i = tid; i < KNUM * VD * VP; i += THREADS) sM[i] = d_M[i];
    if (tid < COUT) sC[tid] = d_Cf[tid];

    const int g = tid >> 5;   // 0..7  : t within tile (one warp per t)
    const int p = tid & 31;   // 0..31 : o-pair index; o0 = 2p, o1 = 2p+1

    for (int tile = blockIdx.x; tile < NTILES; tile += gridDim.x) {
        int n  = tile >> 5;            // TLEN/TT = 32 tiles per n
        int t0 = (tile & 31) * TT;

        __syncthreads();  // protects sx reuse (and first-iter param fill)

        // load x tile: x[n][c][t0..t0+TT-1][0..17] -> sx[t][c][VP]
        const float* xn = x + (size_t)n * (CIN * TLEN * VD) + (size_t)t0 * VD;
        for (int i = tid; i < CIN * TT * VD; i += THREADS) {
            int c = i / (TT * VD);
            int j = i - c * (TT * VD);
            int t = j / VD;
            int v = j - t * VD;
            sx[(t * CIN + c) * VP + v] = xn[c * (TLEN * VD) + j];
        }
        __syncthreads();

        // ---- stage A: Y{0,1}[k][v] = sum_c Weff[k][o,c] * x[c,v]
        unsigned long long Y0[KNUM][9], Y1[KNUM][9];
#pragma unroll
        for (int k = 0; k < KNUM; k++)
#pragma unroll
            for (int q = 0; q < 9; q++) { Y0[k][q] = 0ull; Y1[k][q] = 0ull; }

        const float* xr = sx + g * (CIN * VP);
#pragma unroll 4
        for (int c = 0; c < CIN; c++) {
            float4 wa = *reinterpret_cast<const float4*>(sW0 + (c * 32 + p) * 4);
            float4 wb = *reinterpret_cast<const float4*>(sW1 + (c * 32 + p) * 4);
            const float* row = xr + c * VP;
            ulonglong2 xA = *reinterpret_cast<const ulonglong2*>(row);
            ulonglong2 xB = *reinterpret_cast<const ulonglong2*>(row + 4);
            ulonglong2 xC = *reinterpret_cast<const ulonglong2*>(row + 8);
            ulonglong2 xD = *reinterpret_cast<const ulonglong2*>(row + 12);
            unsigned long long xE = *reinterpret_cast<const unsigned long long*>(row + 16);
            unsigned long long a0 = pk2(wa.x, wa.x);
            unsigned long long a1 = pk2(wa.y, wa.y);
            unsigned long long a2 = pk2(wa.z, wa.z);
            unsigned long long b0 = pk2(wb.x, wb.x);
            unsigned long long b1 = pk2(wb.y, wb.y);
            unsigned long long b2 = pk2(wb.z, wb.z);
            unsigned long long xs[9] = {xA.x, xA.y, xB.x, xB.y, xC.x, xC.y, xD.x, xD.y, xE};
#pragma unroll
            for (int q = 0; q < 9; q++) {
                Y0[0][q] = fma2(a0, xs[q], Y0[0][q]);
                Y0[1][q] = fma2(a1, xs[q], Y0[1][q]);
                Y0[2][q] = fma2(a2, xs[q], Y0[2][q]);
                Y1[0][q] = fma2(b0, xs[q], Y1[0][q]);
                Y1[1][q] = fma2(b1, xs[q], Y1[1][q]);
                Y1[2][q] = fma2(b2, xs[q], Y1[2][q]);
            }
        }

        // ---- stage B: O{0,1}[w] = Ceff[o] + sum_k sum_v Y[k][v] * M_k[v][w]
        float cf0 = sC[2 * p];
        float cf1 = sC[2 * p + 1];
        unsigned long long O0[9], O1[9];
        {
            unsigned long long c0 = pk2(cf0, cf0);
            unsigned long long c1 = pk2(cf1, cf1);
#pragma unroll
            for (int q = 0; q < 9; q++) { O0[q] = c0; O1[q] = c1; }
        }

#pragma unroll
        for (int k = 0; k < KNUM; k++) {
#pragma unroll
            for (int pv = 0; pv < 9; pv++) {
                float y0a, y0b, y1a, y1b;
                upk2(Y0[k][pv], y0a, y0b);
                upk2(Y1[k][pv], y1a, y1b);
                unsigned long long Ya0 = pk2(y0a, y0a);
                unsigned long long Ya1 = pk2(y1a, y1a);
                const float* m0 = sM + (k * VD + 2 * pv) * VP;
                {   // M row (2*pv): multiplies the even-v half of Y
                    ulonglong2 r0 = *reinterpret_cast<const ulonglong2*>(m0);
                    ulonglong2 r1 = *reinterpret_cast<const ulonglong2*>(m0 + 4);
                    ulonglong2 r2 = *reinterpret_cast<const ulonglong2*>(m0 + 8);
                    ulonglong2 r3 = *reinterpret_cast<const ulonglong2*>(m0 + 12);
                    unsigned long long r4 = *reinterpret_cast<const unsigned long long*>(m0 + 16);
                    O0[0] = fma2(Ya0, r0.x, O0[0]); O1[0] = fma2(Ya1, r0.x, O1[0]);
                    O0[1] = fma2(Ya0, r0.y, O0[1]); O1[1] = fma2(Ya1, r0.y, O1[1]);
                    O0[2] = fma2(Ya0, r1.x, O0[2]); O1[2] = fma2(Ya1, r1.x, O1[2]);
                    O0[3] = fma2(Ya0, r1.y, O0[3]); O1[3] = fma2(Ya1, r1.y, O1[3]);
                    O0[4] = fma2(Ya0, r2.x, O0[4]); O1[4] = fma2(Ya1, r2.x, O1[4]);
                    O0[5] = fma2(Ya0, r2.y, O0[5]); O1[5] = fma2(Ya1, r2.y, O1[5]);
                    O0[6] = fma2(Ya0, r3.x, O0[6]); O1[6] = fma2(Ya1, r3.x, O1[6]);
                    O0[7] = fma2(Ya0, r3.y, O0[7]); O1[7] = fma2(Ya1, r3.y, O1[7]);
                    O0[8] = fma2(Ya0, r4,   O0[8]); O1[8] = fma2(Ya1, r4,   O1[8]);
                }
                unsigned long long Yb0 = pk2(y0b, y0b);
                unsigned long long Yb1 = pk2(y1b, y1b);
                const float* m1 = m0 + VP;
                {   // M row (2*pv+1): multiplies the odd-v half of Y
                    ulonglong2 r0 = *reinterpret_cast<const ulonglong2*>(m1);
                    ulonglong2 r1 = *reinterpret_cast<const ulonglong2*>(m1 + 4);
                    ulonglong2 r2 = *reinterpret_cast<const ulonglong2*>(m1 + 8);
                    ulonglong2 r3 = *reinterpret_cast<const ulonglong2*>(m1 + 12);
                    unsigned long long r4 = *reinterpret_cast<const unsigned long long*>(m1 + 16);
                    O0[0] = fma2(Yb0, r0.x, O0[0]); O1[0] = fma2(Yb1, r0.x, O1[0]);
                    O0[1] = fma2(Yb0, r0.y, O0[1]); O1[1] = fma2(Yb1, r0.y, O1[1]);
                    O0[2] = fma2(Yb0, r1.x, O0[2]); O1[2] = fma2(Yb1, r1.x, O1[2]);
                    O0[3] = fma2(Yb0, r1.y, O0[3]); O1[3] = fma2(Yb1, r1.y, O1[3]);
                    O0[4] = fma2(Yb0, r2.x, O0[4]); O1[4] = fma2(Yb1, r2.x, O1[4]);
                    O0[5] = fma2(Yb0, r2.y, O0[5]); O1[5] = fma2(Yb1, r2.y, O1[5]);
                    O0[6] = fma2(Yb0, r3.x, O0[6]); O1[6] = fma2(Yb1, r3.x, O1[6]);
                    O0[7] = fma2(Yb0, r3.y, O0[7]); O1[7] = fma2(Yb1, r3.y, O1[7]);
                    O0[8] = fma2(Yb0, r4,   O0[8]); O1[8] = fma2(Yb1, r4,   O1[8]);
                }
            }
        }

        // ---- epilogue: relu + store (8B float2 stores), 2 channels
        float* op0 = out + ((size_t)(n * COUT + 2 * p) * TLEN + (t0 + g)) * VD;
        float* op1 = op0 + (size_t)TLEN * VD;
#pragma unroll
        for (int q = 0; q < 9; q++) {
            float a, b;
            upk2(O0[q], a, b);
            *reinterpret_cast<float2*>(op0 + 2 * q) =
                make_float2(fmaxf(a, 0.0f), fmaxf(b, 0.0f));
            upk2(O1[q], a, b);
            *reinterpret_cast<float2*>(op1 + 2 * q) =
                make_float2(fmaxf(a, 0.0f), fmaxf(b, 0.0f));
        }
    }
}

static const int SMEM_BYTES =
    (CIN * 32 * 4 * 2 + KNUM * VD * VP + COUT + TT * CIN * VP) * 4;

extern "C" void kernel_launch(void* const* d_in, const int* in_sizes, int n_in,
                              void* d_out, int out_size)
{
    (void)in_sizes; (void)n_in; (void)out_size;
    const float* x    = (const float*)d_in[0];
    const float* A    = (const float*)d_in[1];
    const float* PA   = (const float*)d_in[2];
    const float* Wta  = (const float*)d_in[3];
    const float* bta  = (const float*)d_in[4];
    const float* g_ta = (const float*)d_in[5];
    const float* b_ta = (const float*)d_in[6];
    const float* m_ta = (const float*)d_in[7];
    const float* v_ta = (const float*)d_in[8];
    // d_in[9..12] = Wsa, bsa, Wsb, bsb : dead branch, unused
    const float* g_bn = (const float*)d_in[13];
    const float* b_bn = (const float*)d_in[14];
    const float* m_bn = (const float*)d_in[15];
    const float* v_bn = (const float*)d_in[16];
    float* out = (float*)d_out;

    cudaFuncSetAttribute(ctrgc_main, cudaFuncAttributeMaxDynamicSharedMemorySize, SMEM_BYTES);

    prep_kernel<<<1, 256>>>(A, PA, Wta, bta, g_ta, b_ta, m_ta, v_ta,
                            g_bn, b_bn, m_bn, v_bn);
    ctrgc_main<<<NBLOCKS, THREADS, SMEM_BYTES>>>(x, out);
}